// round 13
// baseline (speedup 1.0000x reference)
#include <cuda_runtime.h>
#include <cstdint>
#include <cstddef>
#include <math.h>

#define BATCH 64
#define SEQ   197
#define NHEAD 12
#define HDIM  64
#define HID   768
#define NTOK  (BATCH*SEQ)   // 12608
#define KPAD  200           // padded k-stride for transposed K tile

typedef unsigned long long ull;

// ---------------- scratch (__device__ globals: no allocation allowed) ----------
__device__ float g_XQ[(size_t)NTOK*HID];
__device__ float g_WQ[(size_t)HID*HID];
__device__ float g_WK[(size_t)HID*HID];
__device__ float g_WV[(size_t)HID*HID];
__device__ float g_WO[(size_t)HID*HID];
__device__ float g_Q [(size_t)NTOK*HID];
__device__ float g_K [(size_t)NTOK*HID];
__device__ float g_V [(size_t)NTOK*HID];
__device__ float g_AQ[(size_t)NTOK*HID];

// ---------------- streams/events for graph fork-join (created at static init) --
struct PipeRes {
    cudaStream_t s1 = nullptr, s2 = nullptr;
    cudaEvent_t  e0 = nullptr, e1 = nullptr, e1end = nullptr, e2end = nullptr;
    bool ok = false;
    PipeRes() {
        if (cudaStreamCreateWithFlags(&s1, cudaStreamNonBlocking) != cudaSuccess) return;
        if (cudaStreamCreateWithFlags(&s2, cudaStreamNonBlocking) != cudaSuccess) return;
        if (cudaEventCreateWithFlags(&e0,    cudaEventDisableTiming) != cudaSuccess) return;
        if (cudaEventCreateWithFlags(&e1,    cudaEventDisableTiming) != cudaSuccess) return;
        if (cudaEventCreateWithFlags(&e1end, cudaEventDisableTiming) != cudaSuccess) return;
        if (cudaEventCreateWithFlags(&e2end, cudaEventDisableTiming) != cudaSuccess) return;
        ok = true;
    }
};
static PipeRes g_pipe;

// ---------------- f32x2 helpers (per-lane identical to scalar rn ops) ----------
__device__ __forceinline__ ull pk2(float a, float b) {
    ull r; asm("mov.b64 %0, {%1, %2};" : "=l"(r) : "f"(a), "f"(b)); return r;
}
__device__ __forceinline__ float2 upk2(ull v) {
    float2 r; asm("mov.b64 {%0, %1}, %2;" : "=f"(r.x), "=f"(r.y) : "l"(v)); return r;
}
__device__ __forceinline__ void fma2(ull &d, ull a, ull b) {
    asm("fma.rn.f32x2 %0, %1, %2, %0;" : "+l"(d) : "l"(a), "l"(b));
}

// ---------------- quantize-dequantize, XLA div->mul replica --------------------
#define INV127 (1.0f/127.0f)

__device__ __forceinline__ float qdq_m(float x, float invKa, float Ka) {
    float t = fminf(fmaxf(__fmul_rn(x, invKa), -1.0f), 1.0f);
    float r = rintf(__fmul_rn(t, 127.0f));
    return __fmul_rn(__fmul_rn(r, INV127), Ka);
}

__global__ void quant4_kernel(const float4* __restrict__ in, float4* __restrict__ out,
                              int n4, float invKa, float Ka) {
    int i = blockIdx.x * blockDim.x + threadIdx.x;
    int stride = gridDim.x * blockDim.x;
    for (; i < n4; i += stride) {
        float4 v = in[i];
        v.x = qdq_m(v.x, invKa, Ka);
        v.y = qdq_m(v.y, invKa, Ka);
        v.z = qdq_m(v.z, invKa, Ka);
        v.w = qdq_m(v.w, invKa, Ka);
        out[i] = v;
    }
}

__global__ void quantw_kernel(const float4* __restrict__ w0, const float4* __restrict__ w1,
                              const float4* __restrict__ w2, const float4* __restrict__ w3,
                              float4* __restrict__ o0, float4* __restrict__ o1,
                              float4* __restrict__ o2, float4* __restrict__ o3,
                              int n4) {
    const float4* in; float4* out;
    switch (blockIdx.y) {
        case 0: in = w0; out = o0; break;
        case 1: in = w1; out = o1; break;
        case 2: in = w2; out = o2; break;
        default: in = w3; out = o3; break;
    }
    int i = blockIdx.x * blockDim.x + threadIdx.x;
    int stride = gridDim.x * blockDim.x;
    for (; i < n4; i += stride) {
        float4 v = in[i];
        v.x = qdq_m(v.x, 10.0f, 0.1f);
        v.y = qdq_m(v.y, 10.0f, 0.1f);
        v.z = qdq_m(v.z, 10.0f, 0.1f);
        v.w = qdq_m(v.w, 10.0f, 0.1f);
        out[i] = v;
    }
}

// ---------------- NT GEMM core (serial ascending-k chain per output) -----------
// Widened B reads: thread owns output columns 8tx..8tx+7 (2x LDS.128 per k).
__device__ __forceinline__ void gemm_nt_body(
    const float* __restrict__ A, const float* __restrict__ W,
    const float* __restrict__ bias, float* __restrict__ C,
    int m0, int n0)
{
    __shared__ __align__(16) float As[16][64 + 4];
    __shared__ __align__(16) float Bs[16][128 + 4];

    const int tid = threadIdx.x;
    const int tx = tid & 15;
    const int ty = tid >> 4;

    const int lr = tid >> 2;
    const int lk = (tid & 3) * 4;

    const float* Ag  = A + (size_t)(m0 + lr) * HID + lk;
    const float* Wg0 = W + (size_t)(n0 + lr) * HID + lk;
    const float* Wg1 = Wg0 + (size_t)64 * HID;

    float4 pa  = *(const float4*)Ag;
    float4 pb0 = *(const float4*)Wg0;
    float4 pb1 = *(const float4*)Wg1;

    ull acc[4][4];
    #pragma unroll
    for (int i = 0; i < 4; i++)
        #pragma unroll
        for (int j = 0; j < 4; j++) acc[i][j] = 0ull;

    #pragma unroll 1
    for (int kt = 0; kt < 48; kt++) {
        __syncthreads();
        As[lk+0][lr] = pa.x;  As[lk+1][lr] = pa.y;
        As[lk+2][lr] = pa.z;  As[lk+3][lr] = pa.w;
        Bs[lk+0][lr] = pb0.x; Bs[lk+1][lr] = pb0.y;
        Bs[lk+2][lr] = pb0.z; Bs[lk+3][lr] = pb0.w;
        Bs[lk+0][lr+64] = pb1.x; Bs[lk+1][lr+64] = pb1.y;
        Bs[lk+2][lr+64] = pb1.z; Bs[lk+3][lr+64] = pb1.w;
        __syncthreads();

        if (kt < 47) {
            pa  = *(const float4*)(Ag  + (kt+1)*16);
            pb0 = *(const float4*)(Wg0 + (kt+1)*16);
            pb1 = *(const float4*)(Wg1 + (kt+1)*16);
        }

        #pragma unroll
        for (int k = 0; k < 16; k++) {
            float4 a4 = *(const float4*)&As[k][ty*4];
            ull ad0 = pk2(a4.x, a4.x);
            ull ad1 = pk2(a4.y, a4.y);
            ull ad2 = pk2(a4.z, a4.z);
            ull ad3 = pk2(a4.w, a4.w);
            ulonglong2 bA = *(const ulonglong2*)&Bs[k][8*tx];
            ulonglong2 bB = *(const ulonglong2*)&Bs[k][8*tx + 4];
            fma2(acc[0][0], ad0, bA.x); fma2(acc[0][1], ad0, bA.y);
            fma2(acc[0][2], ad0, bB.x); fma2(acc[0][3], ad0, bB.y);
            fma2(acc[1][0], ad1, bA.x); fma2(acc[1][1], ad1, bA.y);
            fma2(acc[1][2], ad1, bB.x); fma2(acc[1][3], ad1, bB.y);
            fma2(acc[2][0], ad2, bA.x); fma2(acc[2][1], ad2, bA.y);
            fma2(acc[2][2], ad2, bB.x); fma2(acc[2][3], ad2, bB.y);
            fma2(acc[3][0], ad3, bA.x); fma2(acc[3][1], ad3, bA.y);
            fma2(acc[3][2], ad3, bB.x); fma2(acc[3][3], ad3, bB.y);
        }
    }

    #pragma unroll
    for (int i = 0; i < 4; i++) {
        int row = m0 + ty*4 + i;
        int col = n0 + 8*tx;
        float2 r0 = upk2(acc[i][0]);
        float2 r1 = upk2(acc[i][1]);
        float2 r2 = upk2(acc[i][2]);
        float2 r3 = upk2(acc[i][3]);
        float4 oA, oB;
        oA.x = __fadd_rn(r0.x, bias[col+0]);
        oA.y = __fadd_rn(r0.y, bias[col+1]);
        oA.z = __fadd_rn(r1.x, bias[col+2]);
        oA.w = __fadd_rn(r1.y, bias[col+3]);
        oB.x = __fadd_rn(r2.x, bias[col+4]);
        oB.y = __fadd_rn(r2.y, bias[col+5]);
        oB.z = __fadd_rn(r3.x, bias[col+6]);
        oB.w = __fadd_rn(r3.y, bias[col+7]);
        *(float4*)&C[(size_t)row * HID + col]     = oA;
        *(float4*)&C[(size_t)row * HID + col + 4] = oB;
    }
}

__global__ __launch_bounds__(256) void gemm_nt_kernel(
    const float* __restrict__ A, const float* __restrict__ W,
    const float* __restrict__ bias, float* __restrict__ C, int m_off)
{
    gemm_nt_body(A, W, bias, C, (m_off + blockIdx.x) * 64, blockIdx.y * 128);
}

__global__ __launch_bounds__(256) void gemm_qkv_kernel(
    const float* __restrict__ A,
    const float* __restrict__ Wq, const float* __restrict__ bq, float* __restrict__ Cq,
    const float* __restrict__ Wk, const float* __restrict__ bk, float* __restrict__ Ck,
    const float* __restrict__ Wv, const float* __restrict__ bv, float* __restrict__ Cv,
    int m_off)
{
    const float* W; const float* bias; float* C;
    switch (blockIdx.z) {
        case 0: W = Wq; bias = bq; C = Cq; break;
        case 1: W = Wk; bias = bk; C = Ck; break;
        default: W = Wv; bias = bv; C = Cv; break;
    }
    gemm_nt_body(A, W, bias, C, (m_off + blockIdx.x) * 64, blockIdx.y * 128);
}

// ---------------- attention: one block per (b,h), bit-identical numerics -------
__global__ __launch_bounds__(256, 2) void attn_kernel(
    const float* __restrict__ Q, const float* __restrict__ K,
    const float* __restrict__ V, float* __restrict__ OQ, int bh_off)
{
    extern __shared__ __align__(16) float sm[];
    float* Kt = sm;                    // [64][KPAD]  (transposed K)
    float* Vs = sm + HDIM * KPAD;      // [197][64]

    const int bh = bh_off + blockIdx.x;
    const int b  = bh / NHEAD;
    const int h  = bh - b * NHEAD;
    const size_t base = (size_t)b * SEQ * HID + (size_t)h * HDIM;

    const float4* Kg = (const float4*)(K + base);
    const float4* Vg = (const float4*)(V + base);
    float4* Vs4 = (float4*)Vs;
    for (int i = threadIdx.x; i < SEQ * (HDIM/4); i += 256) {
        int r = i >> 4, c4 = (i & 15) * 4;
        size_t g = (size_t)r * (HID/4) + (c4 >> 2);
        float4 kv = Kg[g];
        Kt[(c4+0)*KPAD + r] = kv.x;
        Kt[(c4+1)*KPAD + r] = kv.y;
        Kt[(c4+2)*KPAD + r] = kv.z;
        Kt[(c4+3)*KPAD + r] = kv.w;
        Vs4[i] = Vg[g];
    }
    __syncthreads();

    const int q = threadIdx.x;
    if (q >= SEQ) return;

    float qr[HDIM];
    {
        const float4* Qp = (const float4*)(Q + base + (size_t)q * HID);
        #pragma unroll
        for (int i = 0; i < 16; i++) {
            float4 t = Qp[i];
            qr[4*i+0] = t.x; qr[4*i+1] = t.y; qr[4*i+2] = t.z; qr[4*i+3] = t.w;
        }
    }

    float sl[SEQ];
    float m = -3.402823466e+38f;

    // scores: 4 k at a time (two f32x2 chains), each lane = serial-d fma.rn chain
    #pragma unroll 1
    for (int k0 = 0; k0 < 196; k0 += 4) {
        ull a01 = 0ull, a23 = 0ull;
        #pragma unroll
        for (int d = 0; d < HDIM; d++) {
            ulonglong2 kk = *(const ulonglong2*)(Kt + d * KPAD + k0);
            ull qd2 = pk2(qr[d], qr[d]);
            fma2(a01, qd2, kk.x);
            fma2(a23, qd2, kk.y);
        }
        float2 s01 = upk2(a01);
        float2 s23 = upk2(a23);
        float v0 = __fmul_rn(s01.x, 0.125f);
        float v1 = __fmul_rn(s01.y, 0.125f);
        float v2 = __fmul_rn(s23.x, 0.125f);
        float v3 = __fmul_rn(s23.y, 0.125f);
        sl[k0+0] = v0; sl[k0+1] = v1; sl[k0+2] = v2; sl[k0+3] = v3;
        m = fmaxf(fmaxf(fmaxf(fmaxf(m, v0), v1), v2), v3);
    }
    {
        float a = 0.0f;
        #pragma unroll
        for (int d = 0; d < HDIM; d++)
            a = fmaf(qr[d], Kt[d * KPAD + 196], a);
        float v = __fmul_rn(a, 0.125f);
        sl[196] = v;
        m = fmaxf(m, v);
    }

    // fused: u = exp(s-m) and strided partial accumulation (XLA order preserved:
    // part[k&31] accumulated in ascending k, then tree 16..1)
    float part[32];
    #pragma unroll
    for (int j = 0; j < 32; j++) part[j] = 0.0f;
    for (int k = 0; k < SEQ; k++) {
        float u = expf(__fadd_rn(sl[k], -m));
        sl[k] = u;
        part[k & 31] = __fadd_rn(part[k & 31], u);
    }
    #pragma unroll
    for (int off = 16; off >= 1; off >>= 1)
        #pragma unroll
        for (int j = 0; j < 16; j++)
            if (j < off) part[j] = __fadd_rn(part[j], part[j + off]);
    const float l = part[0];

    // PV with fused division, 2-k unroll for div ILP; per-column chains stay
    // ascending-k serial fma.rn
    ull acc[32];
    #pragma unroll
    for (int i = 0; i < 32; i++) acc[i] = 0ull;

    const ulonglong2* V2 = (const ulonglong2*)Vs;
    #pragma unroll 1
    for (int k = 0; k < 196; k += 2) {
        float p0 = __fdiv_rn(sl[k],   l);
        float p1 = __fdiv_rn(sl[k+1], l);
        ull pd0 = pk2(p0, p0);
        ull pd1 = pk2(p1, p1);
        const ulonglong2* vr0 = V2 + (size_t)k * 16;
        const ulonglong2* vr1 = vr0 + 16;
        #pragma unroll
        for (int i = 0; i < 16; i++) {
            ulonglong2 t0 = vr0[i];
            fma2(acc[2*i],   pd0, t0.x);
            fma2(acc[2*i+1], pd0, t0.y);
        }
        #pragma unroll
        for (int i = 0; i < 16; i++) {
            ulonglong2 t1 = vr1[i];
            fma2(acc[2*i],   pd1, t1.x);
            fma2(acc[2*i+1], pd1, t1.y);
        }
    }
    {
        float p = __fdiv_rn(sl[196], l);
        ull pd = pk2(p, p);
        const ulonglong2* vr = V2 + (size_t)196 * 16;
        #pragma unroll
        for (int i = 0; i < 16; i++) {
            ulonglong2 t = vr[i];
            fma2(acc[2*i],   pd, t.x);
            fma2(acc[2*i+1], pd, t.y);
        }
    }

    float* dst = OQ + base + (size_t)q * HID;
    #pragma unroll
    for (int i = 0; i < 32; i++) {
        float2 v = upk2(acc[i]);
        dst[2*i]   = qdq_m(v.x, 0.25f, 4.0f);
        dst[2*i+1] = qdq_m(v.y, 0.25f, 4.0f);
    }
}

// ---------------- launch: batch-split fork/join pipeline ------------------------
extern "C" void kernel_launch(void* const* d_in, const int* in_sizes, int n_in,
                              void* d_out, int out_size) {
    const float* x  = (const float*)d_in[0];
    const float* wq = (const float*)d_in[1];
    const float* bq = (const float*)d_in[2];
    const float* wk = (const float*)d_in[3];
    const float* bk = (const float*)d_in[4];
    const float* wv = (const float*)d_in[5];
    const float* bv = (const float*)d_in[6];
    const float* wo = (const float*)d_in[7];
    const float* bo = (const float*)d_in[8];
    float* out = (float*)d_out;

    float *XQ, *WQ, *WK, *WV, *WO, *Qb, *Kb, *Vb, *AQ;
    cudaGetSymbolAddress((void**)&XQ, g_XQ);
    cudaGetSymbolAddress((void**)&WQ, g_WQ);
    cudaGetSymbolAddress((void**)&WK, g_WK);
    cudaGetSymbolAddress((void**)&WV, g_WV);
    cudaGetSymbolAddress((void**)&WO, g_WO);
    cudaGetSymbolAddress((void**)&Qb, g_Q);
    cudaGetSymbolAddress((void**)&Kb, g_K);
    cudaGetSymbolAddress((void**)&Vb, g_V);
    cudaGetSymbolAddress((void**)&AQ, g_AQ);

    const int nX4 = NTOK * HID / 4;
    const int nW4 = HID * HID / 4;
    const int attn_smem = (HDIM * KPAD + SEQ * HDIM) * (int)sizeof(float);  // 101,632 B
    cudaFuncSetAttribute(attn_kernel, cudaFuncAttributeMaxDynamicSharedMemorySize, attn_smem);

    if (g_pipe.ok) {
        cudaStream_t s1 = g_pipe.s1, s2 = g_pipe.s2;

        // S0: quantize
        quant4_kernel<<<(nX4 + 255)/256, 256>>>((const float4*)x, (float4*)XQ, nX4, 0.25f, 4.0f);
        {
            dim3 wgrid((nW4 + 255)/256, 4);
            quantw_kernel<<<wgrid, 256>>>((const float4*)wq, (const float4*)wk,
                                          (const float4*)wv, (const float4*)wo,
                                          (float4*)WQ, (float4*)WK, (float4*)WV, (float4*)WO, nW4);
        }
        cudaEventRecord(g_pipe.e0, 0);

        // S1: QKV-A (row blocks 0..98 -> rows 0..6335, covers batches 0..31)
        cudaStreamWaitEvent(s1, g_pipe.e0, 0);
        {
            dim3 ga(99, 6, 3);
            gemm_qkv_kernel<<<ga, 256, 0, s1>>>(XQ, WQ, bq, Qb, WK, bk, Kb, WV, bv, Vb, 0);
        }
        cudaEventRecord(g_pipe.e1, s1);

        // S2: QKV-B (row blocks 99..196)
        cudaStreamWaitEvent(s2, g_pipe.e1, 0);
        {
            dim3 gb(98, 6, 3);
            gemm_qkv_kernel<<<gb, 256, 0, s2>>>(XQ, WQ, bq, Qb, WK, bk, Kb, WV, bv, Vb, 99);
        }

        // S1: attn-A (batches 0..31) then Ogemm-A (row blocks 0..97, rows<6272)
        attn_kernel<<<384, 256, attn_smem, s1>>>(Qb, Kb, Vb, AQ, 0);
        {
            dim3 goa(98, 6);
            gemm_nt_kernel<<<goa, 256, 0, s1>>>(AQ, WO, bo, out, 0);
        }
        cudaEventRecord(g_pipe.e1end, s1);

        // S2: attn-B (batches 32..63)
        attn_kernel<<<384, 256, attn_smem, s2>>>(Qb, Kb, Vb, AQ, 384);
        cudaEventRecord(g_pipe.e2end, s2);

        // S0: join, then Ogemm-B (row blocks 98..196)
        cudaStreamWaitEvent(0, g_pipe.e1end, 0);
        cudaStreamWaitEvent(0, g_pipe.e2end, 0);
        {
            dim3 gob(99, 6);
            gemm_nt_kernel<<<gob, 256>>>(AQ, WO, bo, out, 98);
        }
    } else {
        // fallback: single-stream serial
        quant4_kernel<<<(nX4 + 255)/256, 256>>>((const float4*)x, (float4*)XQ, nX4, 0.25f, 4.0f);
        dim3 wgrid((nW4 + 255)/256, 4);
        quantw_kernel<<<wgrid, 256>>>((const float4*)wq, (const float4*)wk,
                                      (const float4*)wv, (const float4*)wo,
                                      (float4*)WQ, (float4*)WK, (float4*)WV, (float4*)WO, nW4);
        dim3 qkvgrid(NTOK/64, HID/128, 3);
        gemm_qkv_kernel<<<qkvgrid, 256>>>(XQ, WQ, bq, Qb, WK, bk, Kb, WV, bv, Vb, 0);
        attn_kernel<<<BATCH * NHEAD, 256, attn_smem>>>(Qb, Kb, Vb, AQ, 0);
        dim3 ggrid(NTOK/64, HID/128);
        gemm_nt_kernel<<<ggrid, 256>>>(AQ, WO, bo, out, 0);
    }
}

// round 14
// speedup vs baseline: 1.3913x; 1.3913x over previous
#include <cuda_runtime.h>
#include <cstdint>
#include <cstddef>
#include <math.h>

#define BATCH 64
#define SEQ   197
#define NHEAD 12
#define HDIM  64
#define HID   768
#define NTOK  (BATCH*SEQ)   // 12608
#define KPAD  200           // padded k-stride for transposed K tile

typedef unsigned long long ull;

// ---------------- scratch (__device__ globals: no allocation allowed) ----------
__device__ float g_XQ[(size_t)NTOK*HID];
__device__ float g_WQ[(size_t)HID*HID];
__device__ float g_WK[(size_t)HID*HID];
__device__ float g_WV[(size_t)HID*HID];
__device__ float g_WO[(size_t)HID*HID];
__device__ float g_Q [(size_t)NTOK*HID];
__device__ float g_K [(size_t)NTOK*HID];
__device__ float g_V [(size_t)NTOK*HID];
__device__ float g_AQ[(size_t)NTOK*HID];

// ---------------- streams/events for graph fork-join (created at static init) --
struct PipeRes {
    cudaStream_t s1 = nullptr, s2 = nullptr;
    cudaEvent_t  e0 = nullptr, e1 = nullptr, e1end = nullptr, e2end = nullptr;
    bool ok = false;
    PipeRes() {
        if (cudaStreamCreateWithFlags(&s1, cudaStreamNonBlocking) != cudaSuccess) return;
        if (cudaStreamCreateWithFlags(&s2, cudaStreamNonBlocking) != cudaSuccess) return;
        if (cudaEventCreateWithFlags(&e0,    cudaEventDisableTiming) != cudaSuccess) return;
        if (cudaEventCreateWithFlags(&e1,    cudaEventDisableTiming) != cudaSuccess) return;
        if (cudaEventCreateWithFlags(&e1end, cudaEventDisableTiming) != cudaSuccess) return;
        if (cudaEventCreateWithFlags(&e2end, cudaEventDisableTiming) != cudaSuccess) return;
        ok = true;
    }
};
static PipeRes g_pipe;

// ---------------- f32x2 helpers (per-lane identical to scalar rn ops) ----------
__device__ __forceinline__ ull pk2(float a, float b) {
    ull r; asm("mov.b64 %0, {%1, %2};" : "=l"(r) : "f"(a), "f"(b)); return r;
}
__device__ __forceinline__ float2 upk2(ull v) {
    float2 r; asm("mov.b64 {%0, %1}, %2;" : "=f"(r.x), "=f"(r.y) : "l"(v)); return r;
}
__device__ __forceinline__ void fma2(ull &d, ull a, ull b) {
    asm("fma.rn.f32x2 %0, %1, %2, %0;" : "+l"(d) : "l"(a), "l"(b));
}

// ---------------- quantize-dequantize, XLA div->mul replica --------------------
#define INV127 (1.0f/127.0f)

__device__ __forceinline__ float qdq_m(float x, float invKa, float Ka) {
    float t = fminf(fmaxf(__fmul_rn(x, invKa), -1.0f), 1.0f);
    float r = rintf(__fmul_rn(t, 127.0f));
    return __fmul_rn(__fmul_rn(r, INV127), Ka);
}

__global__ void quant4_kernel(const float4* __restrict__ in, float4* __restrict__ out,
                              int n4, float invKa, float Ka) {
    int i = blockIdx.x * blockDim.x + threadIdx.x;
    int stride = gridDim.x * blockDim.x;
    for (; i < n4; i += stride) {
        float4 v = in[i];
        v.x = qdq_m(v.x, invKa, Ka);
        v.y = qdq_m(v.y, invKa, Ka);
        v.z = qdq_m(v.z, invKa, Ka);
        v.w = qdq_m(v.w, invKa, Ka);
        out[i] = v;
    }
}

__global__ void quantw_kernel(const float4* __restrict__ w0, const float4* __restrict__ w1,
                              const float4* __restrict__ w2, const float4* __restrict__ w3,
                              float4* __restrict__ o0, float4* __restrict__ o1,
                              float4* __restrict__ o2, float4* __restrict__ o3,
                              int n4) {
    const float4* in; float4* out;
    switch (blockIdx.y) {
        case 0: in = w0; out = o0; break;
        case 1: in = w1; out = o1; break;
        case 2: in = w2; out = o2; break;
        default: in = w3; out = o3; break;
    }
    int i = blockIdx.x * blockDim.x + threadIdx.x;
    int stride = gridDim.x * blockDim.x;
    for (; i < n4; i += stride) {
        float4 v = in[i];
        v.x = qdq_m(v.x, 10.0f, 0.1f);
        v.y = qdq_m(v.y, 10.0f, 0.1f);
        v.z = qdq_m(v.z, 10.0f, 0.1f);
        v.w = qdq_m(v.w, 10.0f, 0.1f);
        out[i] = v;
    }
}

// ---------------- NT GEMM core (R12-proven: conflict-free B reads) -------------
__device__ __forceinline__ void gemm_nt_body(
    const float* __restrict__ A, const float* __restrict__ W,
    const float* __restrict__ bias, float* __restrict__ C,
    int m0, int n0)
{
    __shared__ __align__(16) float As[16][64 + 4];
    __shared__ __align__(16) float Bs[16][128 + 4];

    const int tid = threadIdx.x;
    const int tx = tid & 15;
    const int ty = tid >> 4;

    const int lr = tid >> 2;
    const int lk = (tid & 3) * 4;

    const float* Ag  = A + (size_t)(m0 + lr) * HID + lk;
    const float* Wg0 = W + (size_t)(n0 + lr) * HID + lk;
    const float* Wg1 = Wg0 + (size_t)64 * HID;

    float4 pa  = *(const float4*)Ag;
    float4 pb0 = *(const float4*)Wg0;
    float4 pb1 = *(const float4*)Wg1;

    ull acc[4][4];
    #pragma unroll
    for (int i = 0; i < 4; i++)
        #pragma unroll
        for (int j = 0; j < 4; j++) acc[i][j] = 0ull;

    #pragma unroll 1
    for (int kt = 0; kt < 48; kt++) {
        __syncthreads();
        As[lk+0][lr] = pa.x;  As[lk+1][lr] = pa.y;
        As[lk+2][lr] = pa.z;  As[lk+3][lr] = pa.w;
        Bs[lk+0][lr] = pb0.x; Bs[lk+1][lr] = pb0.y;
        Bs[lk+2][lr] = pb0.z; Bs[lk+3][lr] = pb0.w;
        Bs[lk+0][lr+64] = pb1.x; Bs[lk+1][lr+64] = pb1.y;
        Bs[lk+2][lr+64] = pb1.z; Bs[lk+3][lr+64] = pb1.w;
        __syncthreads();

        if (kt < 47) {
            pa  = *(const float4*)(Ag  + (kt+1)*16);
            pb0 = *(const float4*)(Wg0 + (kt+1)*16);
            pb1 = *(const float4*)(Wg1 + (kt+1)*16);
        }

        #pragma unroll
        for (int k = 0; k < 16; k++) {
            float4 a4 = *(const float4*)&As[k][ty*4];
            ull ad0 = pk2(a4.x, a4.x);
            ull ad1 = pk2(a4.y, a4.y);
            ull ad2 = pk2(a4.z, a4.z);
            ull ad3 = pk2(a4.w, a4.w);
            ull b[4];
            #pragma unroll
            for (int j = 0; j < 4; j++)
                b[j] = *(const ull*)&Bs[k][32*j + 2*tx];
            #pragma unroll
            for (int j = 0; j < 4; j++) {
                fma2(acc[0][j], ad0, b[j]);
                fma2(acc[1][j], ad1, b[j]);
                fma2(acc[2][j], ad2, b[j]);
                fma2(acc[3][j], ad3, b[j]);
            }
        }
    }

    #pragma unroll
    for (int i = 0; i < 4; i++) {
        int row = m0 + ty*4 + i;
        #pragma unroll
        for (int j = 0; j < 4; j++) {
            int col = n0 + 32*j + 2*tx;
            float2 r = upk2(acc[i][j]);
            float2 o;
            o.x = __fadd_rn(r.x, bias[col]);
            o.y = __fadd_rn(r.y, bias[col+1]);
            *(float2*)&C[(size_t)row * HID + col] = o;
        }
    }
}

__global__ __launch_bounds__(256) void gemm_nt_kernel(
    const float* __restrict__ A, const float* __restrict__ W,
    const float* __restrict__ bias, float* __restrict__ C, int m_off)
{
    gemm_nt_body(A, W, bias, C, (m_off + blockIdx.x) * 64, blockIdx.y * 128);
}

__global__ __launch_bounds__(256) void gemm_qkv_kernel(
    const float* __restrict__ A,
    const float* __restrict__ Wq, const float* __restrict__ bq, float* __restrict__ Cq,
    const float* __restrict__ Wk, const float* __restrict__ bk, float* __restrict__ Ck,
    const float* __restrict__ Wv, const float* __restrict__ bv, float* __restrict__ Cv,
    int m_off)
{
    const float* W; const float* bias; float* C;
    switch (blockIdx.z) {
        case 0: W = Wq; bias = bq; C = Cq; break;
        case 1: W = Wk; bias = bk; C = Ck; break;
        default: W = Wv; bias = bv; C = Cv; break;
    }
    gemm_nt_body(A, W, bias, C, (m_off + blockIdx.x) * 64, blockIdx.y * 128);
}

// ---------------- attention: one block per (b,h), bit-identical numerics -------
__global__ __launch_bounds__(256, 2) void attn_kernel(
    const float* __restrict__ Q, const float* __restrict__ K,
    const float* __restrict__ V, float* __restrict__ OQ, int bh_off)
{
    extern __shared__ __align__(16) float sm[];
    float* Kt = sm;                    // [64][KPAD]  (transposed K)
    float* Vs = sm + HDIM * KPAD;      // [197][64]

    const int bh = bh_off + blockIdx.x;
    const int b  = bh / NHEAD;
    const int h  = bh - b * NHEAD;
    const size_t base = (size_t)b * SEQ * HID + (size_t)h * HDIM;

    const float4* Kg = (const float4*)(K + base);
    const float4* Vg = (const float4*)(V + base);
    float4* Vs4 = (float4*)Vs;
    for (int i = threadIdx.x; i < SEQ * (HDIM/4); i += 256) {
        int r = i >> 4, c4 = (i & 15) * 4;
        size_t g = (size_t)r * (HID/4) + (c4 >> 2);
        float4 kv = Kg[g];
        Kt[(c4+0)*KPAD + r] = kv.x;
        Kt[(c4+1)*KPAD + r] = kv.y;
        Kt[(c4+2)*KPAD + r] = kv.z;
        Kt[(c4+3)*KPAD + r] = kv.w;
        Vs4[i] = Vg[g];
    }
    __syncthreads();

    const int q = threadIdx.x;
    if (q >= SEQ) return;

    float qr[HDIM];
    {
        const float4* Qp = (const float4*)(Q + base + (size_t)q * HID);
        #pragma unroll
        for (int i = 0; i < 16; i++) {
            float4 t = Qp[i];
            qr[4*i+0] = t.x; qr[4*i+1] = t.y; qr[4*i+2] = t.z; qr[4*i+3] = t.w;
        }
    }

    float sl[SEQ];
    float m = -3.402823466e+38f;

    // scores: 4 k at a time (two f32x2 chains), each lane = serial-d fma.rn chain
    #pragma unroll 1
    for (int k0 = 0; k0 < 196; k0 += 4) {
        ull a01 = 0ull, a23 = 0ull;
        #pragma unroll
        for (int d = 0; d < HDIM; d++) {
            ulonglong2 kk = *(const ulonglong2*)(Kt + d * KPAD + k0);
            ull qd2 = pk2(qr[d], qr[d]);
            fma2(a01, qd2, kk.x);
            fma2(a23, qd2, kk.y);
        }
        float2 s01 = upk2(a01);
        float2 s23 = upk2(a23);
        float v0 = __fmul_rn(s01.x, 0.125f);
        float v1 = __fmul_rn(s01.y, 0.125f);
        float v2 = __fmul_rn(s23.x, 0.125f);
        float v3 = __fmul_rn(s23.y, 0.125f);
        sl[k0+0] = v0; sl[k0+1] = v1; sl[k0+2] = v2; sl[k0+3] = v3;
        m = fmaxf(fmaxf(fmaxf(fmaxf(m, v0), v1), v2), v3);
    }
    {
        float a = 0.0f;
        #pragma unroll
        for (int d = 0; d < HDIM; d++)
            a = fmaf(qr[d], Kt[d * KPAD + 196], a);
        float v = __fmul_rn(a, 0.125f);
        sl[196] = v;
        m = fmaxf(m, v);
    }

    // fused: u = exp(s-m) + strided partials (XLA order), then tree 16..1
    float part[32];
    #pragma unroll
    for (int j = 0; j < 32; j++) part[j] = 0.0f;
    for (int k = 0; k < SEQ; k++) {
        float u = expf(__fadd_rn(sl[k], -m));
        sl[k] = u;
        part[k & 31] = __fadd_rn(part[k & 31], u);
    }
    #pragma unroll
    for (int off = 16; off >= 1; off >>= 1)
        #pragma unroll
        for (int j = 0; j < 16; j++)
            if (j < off) part[j] = __fadd_rn(part[j], part[j + off]);
    const float l = part[0];

    // PV with fused division, 2-k unroll; per-column ascending-k serial fma.rn
    ull acc[32];
    #pragma unroll
    for (int i = 0; i < 32; i++) acc[i] = 0ull;

    const ulonglong2* V2 = (const ulonglong2*)Vs;
    #pragma unroll 1
    for (int k = 0; k < 196; k += 2) {
        float p0 = __fdiv_rn(sl[k],   l);
        float p1 = __fdiv_rn(sl[k+1], l);
        ull pd0 = pk2(p0, p0);
        ull pd1 = pk2(p1, p1);
        const ulonglong2* vr0 = V2 + (size_t)k * 16;
        const ulonglong2* vr1 = vr0 + 16;
        #pragma unroll
        for (int i = 0; i < 16; i++) {
            ulonglong2 t0 = vr0[i];
            fma2(acc[2*i],   pd0, t0.x);
            fma2(acc[2*i+1], pd0, t0.y);
        }
        #pragma unroll
        for (int i = 0; i < 16; i++) {
            ulonglong2 t1 = vr1[i];
            fma2(acc[2*i],   pd1, t1.x);
            fma2(acc[2*i+1], pd1, t1.y);
        }
    }
    {
        float p = __fdiv_rn(sl[196], l);
        ull pd = pk2(p, p);
        const ulonglong2* vr = V2 + (size_t)196 * 16;
        #pragma unroll
        for (int i = 0; i < 16; i++) {
            ulonglong2 t = vr[i];
            fma2(acc[2*i],   pd, t.x);
            fma2(acc[2*i+1], pd, t.y);
        }
    }

    float* dst = OQ + base + (size_t)q * HID;
    #pragma unroll
    for (int i = 0; i < 32; i++) {
        float2 v = upk2(acc[i]);
        dst[2*i]   = qdq_m(v.x, 0.25f, 4.0f);
        dst[2*i+1] = qdq_m(v.y, 0.25f, 4.0f);
    }
}

// ---------------- launch: batch-split fork/join pipeline ------------------------
extern "C" void kernel_launch(void* const* d_in, const int* in_sizes, int n_in,
                              void* d_out, int out_size) {
    const float* x  = (const float*)d_in[0];
    const float* wq = (const float*)d_in[1];
    const float* bq = (const float*)d_in[2];
    const float* wk = (const float*)d_in[3];
    const float* bk = (const float*)d_in[4];
    const float* wv = (const float*)d_in[5];
    const float* bv = (const float*)d_in[6];
    const float* wo = (const float*)d_in[7];
    const float* bo = (const float*)d_in[8];
    float* out = (float*)d_out;

    float *XQ, *WQ, *WK, *WV, *WO, *Qb, *Kb, *Vb, *AQ;
    cudaGetSymbolAddress((void**)&XQ, g_XQ);
    cudaGetSymbolAddress((void**)&WQ, g_WQ);
    cudaGetSymbolAddress((void**)&WK, g_WK);
    cudaGetSymbolAddress((void**)&WV, g_WV);
    cudaGetSymbolAddress((void**)&WO, g_WO);
    cudaGetSymbolAddress((void**)&Qb, g_Q);
    cudaGetSymbolAddress((void**)&Kb, g_K);
    cudaGetSymbolAddress((void**)&Vb, g_V);
    cudaGetSymbolAddress((void**)&AQ, g_AQ);

    const int nX4 = NTOK * HID / 4;
    const int nW4 = HID * HID / 4;
    const int attn_smem = (HDIM * KPAD + SEQ * HDIM) * (int)sizeof(float);  // 101,632 B
    cudaFuncSetAttribute(attn_kernel, cudaFuncAttributeMaxDynamicSharedMemorySize, attn_smem);

    if (g_pipe.ok) {
        cudaStream_t s1 = g_pipe.s1, s2 = g_pipe.s2;

        // S0: quantize
        quant4_kernel<<<(nX4 + 255)/256, 256>>>((const float4*)x, (float4*)XQ, nX4, 0.25f, 4.0f);
        {
            dim3 wgrid((nW4 + 255)/256, 4);
            quantw_kernel<<<wgrid, 256>>>((const float4*)wq, (const float4*)wk,
                                          (const float4*)wv, (const float4*)wo,
                                          (float4*)WQ, (float4*)WK, (float4*)WV, (float4*)WO, nW4);
        }
        cudaEventRecord(g_pipe.e0, 0);

        // S1: QKV-A (row blocks 0..98 -> rows 0..6335 -> covers batches 0..31)
        cudaStreamWaitEvent(s1, g_pipe.e0, 0);
        {
            dim3 ga(99, 6, 3);
            gemm_qkv_kernel<<<ga, 256, 0, s1>>>(XQ, WQ, bq, Qb, WK, bk, Kb, WV, bv, Vb, 0);
        }
        cudaEventRecord(g_pipe.e1, s1);

        // S2: QKV-B (row blocks 99..196) — runs while attn-A runs on s1
        cudaStreamWaitEvent(s2, g_pipe.e1, 0);
        {
            dim3 gb(98, 6, 3);
            gemm_qkv_kernel<<<gb, 256, 0, s2>>>(XQ, WQ, bq, Qb, WK, bk, Kb, WV, bv, Vb, 99);
        }

        // S1: attn-A (batches 0..31) then Ogemm-A (row blocks 0..97, rows<6272)
        attn_kernel<<<384, 256, attn_smem, s1>>>(Qb, Kb, Vb, AQ, 0);
        {
            dim3 goa(98, 6);
            gemm_nt_kernel<<<goa, 256, 0, s1>>>(AQ, WO, bo, out, 0);
        }
        cudaEventRecord(g_pipe.e1end, s1);

        // S2: attn-B (batches 32..63)
        attn_kernel<<<384, 256, attn_smem, s2>>>(Qb, Kb, Vb, AQ, 384);
        cudaEventRecord(g_pipe.e2end, s2);

        // S0: join, then Ogemm-B (row blocks 98..196)
        cudaStreamWaitEvent(0, g_pipe.e1end, 0);
        cudaStreamWaitEvent(0, g_pipe.e2end, 0);
        {
            dim3 gob(99, 6);
            gemm_nt_kernel<<<gob, 256>>>(AQ, WO, bo, out, 98);
        }
    } else {
        // fallback: single-stream serial
        quant4_kernel<<<(nX4 + 255)/256, 256>>>((const float4*)x, (float4*)XQ, nX4, 0.25f, 4.0f);
        dim3 wgrid((nW4 + 255)/256, 4);
        quantw_kernel<<<wgrid, 256>>>((const float4*)wq, (const float4*)wk,
                                      (const float4*)wv, (const float4*)wo,
                                      (float4*)WQ, (float4*)WK, (float4*)WV, (float4*)WO, nW4);
        dim3 qkvgrid(NTOK/64, HID/128, 3);
        gemm_qkv_kernel<<<qkvgrid, 256>>>(XQ, WQ, bq, Qb, WK, bk, Kb, WV, bv, Vb, 0);
        attn_kernel<<<BATCH * NHEAD, 256, attn_smem>>>(Qb, Kb, Vb, AQ, 0);
        dim3 ggrid(NTOK/64, HID/128);
        gemm_nt_kernel<<<ggrid, 256>>>(AQ, WO, bo, out, 0);
    }
}

// round 15
// speedup vs baseline: 1.4354x; 1.0317x over previous
#include <cuda_runtime.h>
#include <cstdint>
#include <cstddef>
#include <math.h>

#define BATCH 64
#define SEQ   197
#define NHEAD 12
#define HDIM  64
#define HID   768
#define NTOK  (BATCH*SEQ)   // 12608
#define KPAD  200           // padded k-stride for transposed K tile

typedef unsigned long long ull;

// ---------------- scratch (__device__ globals: no allocation allowed) ----------
__device__ float g_XQ[(size_t)NTOK*HID];
__device__ float g_WQ[(size_t)HID*HID];
__device__ float g_WK[(size_t)HID*HID];
__device__ float g_WV[(size_t)HID*HID];
__device__ float g_WO[(size_t)HID*HID];
__device__ float g_Q [(size_t)NTOK*HID];
__device__ float g_K [(size_t)NTOK*HID];
__device__ float g_V [(size_t)NTOK*HID];
__device__ float g_AQ[(size_t)NTOK*HID];

// ---------------- f32x2 helpers (per-lane identical to scalar rn ops) ----------
__device__ __forceinline__ ull pk2(float a, float b) {
    ull r; asm("mov.b64 %0, {%1, %2};" : "=l"(r) : "f"(a), "f"(b)); return r;
}
__device__ __forceinline__ float2 upk2(ull v) {
    float2 r; asm("mov.b64 {%0, %1}, %2;" : "=f"(r.x), "=f"(r.y) : "l"(v)); return r;
}
__device__ __forceinline__ void fma2(ull &d, ull a, ull b) {
    asm("fma.rn.f32x2 %0, %1, %2, %0;" : "+l"(d) : "l"(a), "l"(b));
}

// ---------------- quantize-dequantize, XLA div->mul replica --------------------
#define INV127 (1.0f/127.0f)

__device__ __forceinline__ float qdq_m(float x, float invKa, float Ka) {
    float t = fminf(fmaxf(__fmul_rn(x, invKa), -1.0f), 1.0f);
    float r = rintf(__fmul_rn(t, 127.0f));
    return __fmul_rn(__fmul_rn(r, INV127), Ka);
}

__global__ void quant4_kernel(const float4* __restrict__ in, float4* __restrict__ out,
                              int n4, float invKa, float Ka) {
    int i = blockIdx.x * blockDim.x + threadIdx.x;
    int stride = gridDim.x * blockDim.x;
    for (; i < n4; i += stride) {
        float4 v = in[i];
        v.x = qdq_m(v.x, invKa, Ka);
        v.y = qdq_m(v.y, invKa, Ka);
        v.z = qdq_m(v.z, invKa, Ka);
        v.w = qdq_m(v.w, invKa, Ka);
        out[i] = v;
    }
}

__global__ void quantw_kernel(const float4* __restrict__ w0, const float4* __restrict__ w1,
                              const float4* __restrict__ w2, const float4* __restrict__ w3,
                              float4* __restrict__ o0, float4* __restrict__ o1,
                              float4* __restrict__ o2, float4* __restrict__ o3,
                              int n4) {
    const float4* in; float4* out;
    switch (blockIdx.y) {
        case 0: in = w0; out = o0; break;
        case 1: in = w1; out = o1; break;
        case 2: in = w2; out = o2; break;
        default: in = w3; out = o3; break;
    }
    int i = blockIdx.x * blockDim.x + threadIdx.x;
    int stride = gridDim.x * blockDim.x;
    for (; i < n4; i += stride) {
        float4 v = in[i];
        v.x = qdq_m(v.x, 10.0f, 0.1f);
        v.y = qdq_m(v.y, 10.0f, 0.1f);
        v.z = qdq_m(v.z, 10.0f, 0.1f);
        v.w = qdq_m(v.w, 10.0f, 0.1f);
        out[i] = v;
    }
}

// ---------------- NT GEMM core: 128x128 tile, 256 thr, 8x8 per thread ----------
// Per output element: strictly serial ascending-k fma.rn chain (bit-exact).
// B smem reads keep the R12-proven conflict-free 32j+2tx LDS.64 pattern.
__device__ __forceinline__ void gemm_nt_body(
    const float* __restrict__ A, const float* __restrict__ W,
    const float* __restrict__ bias, float* __restrict__ C,
    int m0, int n0)
{
    __shared__ __align__(16) float As[16][128 + 4];
    __shared__ __align__(16) float Bs[16][128 + 4];

    const int tid = threadIdx.x;
    const int tx = tid & 15;           // col group: cols 32j + 2tx
    const int ty = tid >> 4;           // row group: rows ty*8 .. ty*8+7

    const int lr = tid >> 1;           // 0..127 (row within tile for loads)
    const int lk = (tid & 1) * 8;      // 0 or 8  (k-offset for loads)

    // clamp ragged last block's loads (results discarded by store guard)
    const int arow = m0 + lr;
    const int arow_c = arow < NTOK ? arow : NTOK - 1;

    const float* Ag = A + (size_t)arow_c * HID + lk;
    const float* Wg = W + (size_t)(n0 + lr) * HID + lk;

    float4 pa0 = *(const float4*)Ag;
    float4 pa1 = *(const float4*)(Ag + 4);
    float4 pb0 = *(const float4*)Wg;
    float4 pb1 = *(const float4*)(Wg + 4);

    ull acc[8][4];
    #pragma unroll
    for (int i = 0; i < 8; i++)
        #pragma unroll
        for (int j = 0; j < 4; j++) acc[i][j] = 0ull;

    #pragma unroll 1
    for (int kt = 0; kt < 48; kt++) {
        __syncthreads();
        As[lk+0][lr] = pa0.x; As[lk+1][lr] = pa0.y;
        As[lk+2][lr] = pa0.z; As[lk+3][lr] = pa0.w;
        As[lk+4][lr] = pa1.x; As[lk+5][lr] = pa1.y;
        As[lk+6][lr] = pa1.z; As[lk+7][lr] = pa1.w;
        Bs[lk+0][lr] = pb0.x; Bs[lk+1][lr] = pb0.y;
        Bs[lk+2][lr] = pb0.z; Bs[lk+3][lr] = pb0.w;
        Bs[lk+4][lr] = pb1.x; Bs[lk+5][lr] = pb1.y;
        Bs[lk+6][lr] = pb1.z; Bs[lk+7][lr] = pb1.w;
        __syncthreads();

        if (kt < 47) {
            pa0 = *(const float4*)(Ag + (kt+1)*16);
            pa1 = *(const float4*)(Ag + (kt+1)*16 + 4);
            pb0 = *(const float4*)(Wg + (kt+1)*16);
            pb1 = *(const float4*)(Wg + (kt+1)*16 + 4);
        }

        #pragma unroll
        for (int k = 0; k < 16; k++) {      // ascending k
            float4 aA = *(const float4*)&As[k][ty*8];
            float4 aB = *(const float4*)&As[k][ty*8 + 4];
            ull b[4];
            #pragma unroll
            for (int j = 0; j < 4; j++)
                b[j] = *(const ull*)&Bs[k][32*j + 2*tx];
            ull ad0 = pk2(aA.x, aA.x);
            ull ad1 = pk2(aA.y, aA.y);
            ull ad2 = pk2(aA.z, aA.z);
            ull ad3 = pk2(aA.w, aA.w);
            ull ad4 = pk2(aB.x, aB.x);
            ull ad5 = pk2(aB.y, aB.y);
            ull ad6 = pk2(aB.z, aB.z);
            ull ad7 = pk2(aB.w, aB.w);
            #pragma unroll
            for (int j = 0; j < 4; j++) {
                fma2(acc[0][j], ad0, b[j]);
                fma2(acc[1][j], ad1, b[j]);
                fma2(acc[2][j], ad2, b[j]);
                fma2(acc[3][j], ad3, b[j]);
                fma2(acc[4][j], ad4, b[j]);
                fma2(acc[5][j], ad5, b[j]);
                fma2(acc[6][j], ad6, b[j]);
                fma2(acc[7][j], ad7, b[j]);
            }
        }
    }

    #pragma unroll
    for (int i = 0; i < 8; i++) {
        int row = m0 + ty*8 + i;
        if (row < NTOK) {
            #pragma unroll
            for (int j = 0; j < 4; j++) {
                int col = n0 + 32*j + 2*tx;
                float2 r = upk2(acc[i][j]);
                float2 o;
                o.x = __fadd_rn(r.x, bias[col]);
                o.y = __fadd_rn(r.y, bias[col+1]);
                *(float2*)&C[(size_t)row * HID + col] = o;
            }
        }
    }
}

__global__ __launch_bounds__(256, 2) void gemm_nt_kernel(
    const float* __restrict__ A, const float* __restrict__ W,
    const float* __restrict__ bias, float* __restrict__ C)
{
    gemm_nt_body(A, W, bias, C, blockIdx.x * 128, blockIdx.y * 128);
}

__global__ __launch_bounds__(256, 2) void gemm_qkv_kernel(
    const float* __restrict__ A,
    const float* __restrict__ Wq, const float* __restrict__ bq, float* __restrict__ Cq,
    const float* __restrict__ Wk, const float* __restrict__ bk, float* __restrict__ Ck,
    const float* __restrict__ Wv, const float* __restrict__ bv, float* __restrict__ Cv)
{
    const float* W; const float* bias; float* C;
    switch (blockIdx.z) {
        case 0: W = Wq; bias = bq; C = Cq; break;
        case 1: W = Wk; bias = bk; C = Ck; break;
        default: W = Wv; bias = bv; C = Cv; break;
    }
    gemm_nt_body(A, W, bias, C, blockIdx.x * 128, blockIdx.y * 128);
}

// ---------------- attention: one block per (b,h), bit-identical numerics -------
__global__ __launch_bounds__(256, 2) void attn_kernel(
    const float* __restrict__ Q, const float* __restrict__ K,
    const float* __restrict__ V, float* __restrict__ OQ)
{
    extern __shared__ __align__(16) float sm[];
    float* Kt = sm;                    // [64][KPAD]  (transposed K)
    float* Vs = sm + HDIM * KPAD;      // [197][64]

    const int bh = blockIdx.x;
    const int b  = bh / NHEAD;
    const int h  = bh - b * NHEAD;
    const size_t base = (size_t)b * SEQ * HID + (size_t)h * HDIM;

    const float4* Kg = (const float4*)(K + base);
    const float4* Vg = (const float4*)(V + base);
    float4* Vs4 = (float4*)Vs;
    for (int i = threadIdx.x; i < SEQ * (HDIM/4); i += 256) {
        int r = i >> 4, c4 = (i & 15) * 4;
        size_t g = (size_t)r * (HID/4) + (c4 >> 2);
        float4 kv = Kg[g];
        Kt[(c4+0)*KPAD + r] = kv.x;
        Kt[(c4+1)*KPAD + r] = kv.y;
        Kt[(c4+2)*KPAD + r] = kv.z;
        Kt[(c4+3)*KPAD + r] = kv.w;
        Vs4[i] = Vg[g];
    }
    __syncthreads();

    const int q = threadIdx.x;
    if (q >= SEQ) return;

    float qr[HDIM];
    {
        const float4* Qp = (const float4*)(Q + base + (size_t)q * HID);
        #pragma unroll
        for (int i = 0; i < 16; i++) {
            float4 t = Qp[i];
            qr[4*i+0] = t.x; qr[4*i+1] = t.y; qr[4*i+2] = t.z; qr[4*i+3] = t.w;
        }
    }

    float sl[SEQ];
    float m = -3.402823466e+38f;

    // scores: 4 k at a time (two f32x2 chains), each lane = serial-d fma.rn chain
    #pragma unroll 1
    for (int k0 = 0; k0 < 196; k0 += 4) {
        ull a01 = 0ull, a23 = 0ull;
        #pragma unroll
        for (int d = 0; d < HDIM; d++) {
            ulonglong2 kk = *(const ulonglong2*)(Kt + d * KPAD + k0);
            ull qd2 = pk2(qr[d], qr[d]);
            fma2(a01, qd2, kk.x);
            fma2(a23, qd2, kk.y);
        }
        float2 s01 = upk2(a01);
        float2 s23 = upk2(a23);
        float v0 = __fmul_rn(s01.x, 0.125f);
        float v1 = __fmul_rn(s01.y, 0.125f);
        float v2 = __fmul_rn(s23.x, 0.125f);
        float v3 = __fmul_rn(s23.y, 0.125f);
        sl[k0+0] = v0; sl[k0+1] = v1; sl[k0+2] = v2; sl[k0+3] = v3;
        m = fmaxf(fmaxf(fmaxf(fmaxf(m, v0), v1), v2), v3);
    }
    {
        float a = 0.0f;
        #pragma unroll
        for (int d = 0; d < HDIM; d++)
            a = fmaf(qr[d], Kt[d * KPAD + 196], a);
        float v = __fmul_rn(a, 0.125f);
        sl[196] = v;
        m = fmaxf(m, v);
    }

    // fused: u = exp(s-m) + strided partials (XLA order), then tree 16..1
    float part[32];
    #pragma unroll
    for (int j = 0; j < 32; j++) part[j] = 0.0f;
    for (int k = 0; k < SEQ; k++) {
        float u = expf(__fadd_rn(sl[k], -m));
        sl[k] = u;
        part[k & 31] = __fadd_rn(part[k & 31], u);
    }
    #pragma unroll
    for (int off = 16; off >= 1; off >>= 1)
        #pragma unroll
        for (int j = 0; j < 16; j++)
            if (j < off) part[j] = __fadd_rn(part[j], part[j + off]);
    const float l = part[0];

    // PV with fused division, 2-k unroll; per-column ascending-k serial fma.rn
    ull acc[32];
    #pragma unroll
    for (int i = 0; i < 32; i++) acc[i] = 0ull;

    const ulonglong2* V2 = (const ulonglong2*)Vs;
    #pragma unroll 1
    for (int k = 0; k < 196; k += 2) {
        float p0 = __fdiv_rn(sl[k],   l);
        float p1 = __fdiv_rn(sl[k+1], l);
        ull pd0 = pk2(p0, p0);
        ull pd1 = pk2(p1, p1);
        const ulonglong2* vr0 = V2 + (size_t)k * 16;
        const ulonglong2* vr1 = vr0 + 16;
        #pragma unroll
        for (int i = 0; i < 16; i++) {
            ulonglong2 t0 = vr0[i];
            fma2(acc[2*i],   pd0, t0.x);
            fma2(acc[2*i+1], pd0, t0.y);
        }
        #pragma unroll
        for (int i = 0; i < 16; i++) {
            ulonglong2 t1 = vr1[i];
            fma2(acc[2*i],   pd1, t1.x);
            fma2(acc[2*i+1], pd1, t1.y);
        }
    }
    {
        float p = __fdiv_rn(sl[196], l);
        ull pd = pk2(p, p);
        const ulonglong2* vr = V2 + (size_t)196 * 16;
        #pragma unroll
        for (int i = 0; i < 16; i++) {
            ulonglong2 t = vr[i];
            fma2(acc[2*i],   pd, t.x);
            fma2(acc[2*i+1], pd, t.y);
        }
    }

    float* dst = OQ + base + (size_t)q * HID;
    #pragma unroll
    for (int i = 0; i < 32; i++) {
        float2 v = upk2(acc[i]);
        dst[2*i]   = qdq_m(v.x, 0.25f, 4.0f);
        dst[2*i+1] = qdq_m(v.y, 0.25f, 4.0f);
    }
}

// ---------------- launch: single stream (fork/join regressed in R14) -----------
extern "C" void kernel_launch(void* const* d_in, const int* in_sizes, int n_in,
                              void* d_out, int out_size) {
    const float* x  = (const float*)d_in[0];
    const float* wq = (const float*)d_in[1];
    const float* bq = (const float*)d_in[2];
    const float* wk = (const float*)d_in[3];
    const float* bk = (const float*)d_in[4];
    const float* wv = (const float*)d_in[5];
    const float* bv = (const float*)d_in[6];
    const float* wo = (const float*)d_in[7];
    const float* bo = (const float*)d_in[8];
    float* out = (float*)d_out;

    float *XQ, *WQ, *WK, *WV, *WO, *Qb, *Kb, *Vb, *AQ;
    cudaGetSymbolAddress((void**)&XQ, g_XQ);
    cudaGetSymbolAddress((void**)&WQ, g_WQ);
    cudaGetSymbolAddress((void**)&WK, g_WK);
    cudaGetSymbolAddress((void**)&WV, g_WV);
    cudaGetSymbolAddress((void**)&WO, g_WO);
    cudaGetSymbolAddress((void**)&Qb, g_Q);
    cudaGetSymbolAddress((void**)&Kb, g_K);
    cudaGetSymbolAddress((void**)&Vb, g_V);
    cudaGetSymbolAddress((void**)&AQ, g_AQ);

    const int nX4 = NTOK * HID / 4;
    const int nW4 = HID * HID / 4;

    // 1) quantize-dequantize: X + 4 weights (fused)
    quant4_kernel<<<(nX4 + 255)/256, 256>>>((const float4*)x, (float4*)XQ, nX4, 0.25f, 4.0f);
    {
        dim3 wgrid((nW4 + 255)/256, 4);
        quantw_kernel<<<wgrid, 256>>>((const float4*)wq, (const float4*)wk,
                                      (const float4*)wv, (const float4*)wo,
                                      (float4*)WQ, (float4*)WK, (float4*)WV, (float4*)WO, nW4);
    }

    // 2) fused Q/K/V projections: 128x128 tiles, 99 ragged m-blocks
    dim3 qkvgrid(99, HID/128, 3);   // (99, 6, 3)
    gemm_qkv_kernel<<<qkvgrid, 256>>>(XQ, WQ, bq, Qb, WK, bk, Kb, WV, bv, Vb);

    // 3) attention; emits dequantized AO
    const int attn_smem = (HDIM * KPAD + SEQ * HDIM) * (int)sizeof(float);  // 101,632 B
    cudaFuncSetAttribute(attn_kernel, cudaFuncAttributeMaxDynamicSharedMemorySize, attn_smem);
    attn_kernel<<<BATCH * NHEAD, 256, attn_smem>>>(Qb, Kb, Vb, AQ);

    // 4) O-projection on dequantized AO
    dim3 ggrid(99, HID/128);        // (99, 6)
    gemm_nt_kernel<<<ggrid, 256>>>(AQ, WO, bo, out);
}

// round 16
// speedup vs baseline: 1.7803x; 1.2402x over previous
#include <cuda_runtime.h>
#include <cstdint>
#include <cstddef>
#include <math.h>

#define BATCH 64
#define SEQ   197
#define NHEAD 12
#define HDIM  64
#define HID   768
#define NTOK  (BATCH*SEQ)   // 12608
#define KPAD  200           // padded k-stride for transposed K tile

typedef unsigned long long ull;

// ---------------- scratch (__device__ globals: no allocation allowed) ----------
__device__ float g_XQ[(size_t)NTOK*HID];
__device__ float g_WQ[(size_t)HID*HID];
__device__ float g_WK[(size_t)HID*HID];
__device__ float g_WV[(size_t)HID*HID];
__device__ float g_WO[(size_t)HID*HID];
__device__ float g_Q [(size_t)NTOK*HID];
__device__ float g_K [(size_t)NTOK*HID];
__device__ float g_V [(size_t)NTOK*HID];
__device__ float g_AQ[(size_t)NTOK*HID];

// ---------------- f32x2 helpers (per-lane identical to scalar rn ops) ----------
__device__ __forceinline__ ull pk2(float a, float b) {
    ull r; asm("mov.b64 %0, {%1, %2};" : "=l"(r) : "f"(a), "f"(b)); return r;
}
__device__ __forceinline__ float2 upk2(ull v) {
    float2 r; asm("mov.b64 {%0, %1}, %2;" : "=f"(r.x), "=f"(r.y) : "l"(v)); return r;
}
__device__ __forceinline__ void fma2(ull &d, ull a, ull b) {
    asm("fma.rn.f32x2 %0, %1, %2, %0;" : "+l"(d) : "l"(a), "l"(b));
}

// ---------------- quantize-dequantize, XLA div->mul replica --------------------
#define INV127 (1.0f/127.0f)

__device__ __forceinline__ float qdq_m(float x, float invKa, float Ka) {
    float t = fminf(fmaxf(__fmul_rn(x, invKa), -1.0f), 1.0f);
    float r = rintf(__fmul_rn(t, 127.0f));
    return __fmul_rn(__fmul_rn(r, INV127), Ka);
}

__global__ void quant4_kernel(const float4* __restrict__ in, float4* __restrict__ out,
                              int n4, float invKa, float Ka) {
    int i = blockIdx.x * blockDim.x + threadIdx.x;
    int stride = gridDim.x * blockDim.x;
    for (; i < n4; i += stride) {
        float4 v = in[i];
        v.x = qdq_m(v.x, invKa, Ka);
        v.y = qdq_m(v.y, invKa, Ka);
        v.z = qdq_m(v.z, invKa, Ka);
        v.w = qdq_m(v.w, invKa, Ka);
        out[i] = v;
    }
}

__global__ void quantw_kernel(const float4* __restrict__ w0, const float4* __restrict__ w1,
                              const float4* __restrict__ w2, const float4* __restrict__ w3,
                              float4* __restrict__ o0, float4* __restrict__ o1,
                              float4* __restrict__ o2, float4* __restrict__ o3,
                              int n4) {
    const float4* in; float4* out;
    switch (blockIdx.y) {
        case 0: in = w0; out = o0; break;
        case 1: in = w1; out = o1; break;
        case 2: in = w2; out = o2; break;
        default: in = w3; out = o3; break;
    }
    int i = blockIdx.x * blockDim.x + threadIdx.x;
    int stride = gridDim.x * blockDim.x;
    for (; i < n4; i += stride) {
        float4 v = in[i];
        v.x = qdq_m(v.x, 10.0f, 0.1f);
        v.y = qdq_m(v.y, 10.0f, 0.1f);
        v.z = qdq_m(v.z, 10.0f, 0.1f);
        v.w = qdq_m(v.w, 10.0f, 0.1f);
        out[i] = v;
    }
}

// ---------------- NT GEMM core: 128x128 tile, 256 thr, 8x8 per thread ----------
// (R15-measured win). Per output: strictly serial ascending-k fma.rn chain.
__device__ __forceinline__ void gemm_nt_body(
    const float* __restrict__ A, const float* __restrict__ W,
    const float* __restrict__ bias, float* __restrict__ C,
    int m0, int n0)
{
    __shared__ __align__(16) float As[16][128 + 4];
    __shared__ __align__(16) float Bs[16][128 + 4];

    const int tid = threadIdx.x;
    const int tx = tid & 15;           // col group: cols 32j + 2tx
    const int ty = tid >> 4;           // row group: rows ty*8 .. ty*8+7

    const int lr = tid >> 1;           // 0..127 (row within tile for loads)
    const int lk = (tid & 1) * 8;      // 0 or 8  (k-offset for loads)

    const int arow = m0 + lr;
    const int arow_c = arow < NTOK ? arow : NTOK - 1;

    const float* Ag = A + (size_t)arow_c * HID + lk;
    const float* Wg = W + (size_t)(n0 + lr) * HID + lk;

    float4 pa0 = *(const float4*)Ag;
    float4 pa1 = *(const float4*)(Ag + 4);
    float4 pb0 = *(const float4*)Wg;
    float4 pb1 = *(const float4*)(Wg + 4);

    ull acc[8][4];
    #pragma unroll
    for (int i = 0; i < 8; i++)
        #pragma unroll
        for (int j = 0; j < 4; j++) acc[i][j] = 0ull;

    #pragma unroll 1
    for (int kt = 0; kt < 48; kt++) {
        __syncthreads();
        As[lk+0][lr] = pa0.x; As[lk+1][lr] = pa0.y;
        As[lk+2][lr] = pa0.z; As[lk+3][lr] = pa0.w;
        As[lk+4][lr] = pa1.x; As[lk+5][lr] = pa1.y;
        As[lk+6][lr] = pa1.z; As[lk+7][lr] = pa1.w;
        Bs[lk+0][lr] = pb0.x; Bs[lk+1][lr] = pb0.y;
        Bs[lk+2][lr] = pb0.z; Bs[lk+3][lr] = pb0.w;
        Bs[lk+4][lr] = pb1.x; Bs[lk+5][lr] = pb1.y;
        Bs[lk+6][lr] = pb1.z; Bs[lk+7][lr] = pb1.w;
        __syncthreads();

        if (kt < 47) {
            pa0 = *(const float4*)(Ag + (kt+1)*16);
            pa1 = *(const float4*)(Ag + (kt+1)*16 + 4);
            pb0 = *(const float4*)(Wg + (kt+1)*16);
            pb1 = *(const float4*)(Wg + (kt+1)*16 + 4);
        }

        #pragma unroll
        for (int k = 0; k < 16; k++) {      // ascending k
            float4 aA = *(const float4*)&As[k][ty*8];
            float4 aB = *(const float4*)&As[k][ty*8 + 4];
            ull b[4];
            #pragma unroll
            for (int j = 0; j < 4; j++)
                b[j] = *(const ull*)&Bs[k][32*j + 2*tx];
            ull ad0 = pk2(aA.x, aA.x);
            ull ad1 = pk2(aA.y, aA.y);
            ull ad2 = pk2(aA.z, aA.z);
            ull ad3 = pk2(aA.w, aA.w);
            ull ad4 = pk2(aB.x, aB.x);
            ull ad5 = pk2(aB.y, aB.y);
            ull ad6 = pk2(aB.z, aB.z);
            ull ad7 = pk2(aB.w, aB.w);
            #pragma unroll
            for (int j = 0; j < 4; j++) {
                fma2(acc[0][j], ad0, b[j]);
                fma2(acc[1][j], ad1, b[j]);
                fma2(acc[2][j], ad2, b[j]);
                fma2(acc[3][j], ad3, b[j]);
                fma2(acc[4][j], ad4, b[j]);
                fma2(acc[5][j], ad5, b[j]);
                fma2(acc[6][j], ad6, b[j]);
                fma2(acc[7][j], ad7, b[j]);
            }
        }
    }

    #pragma unroll
    for (int i = 0; i < 8; i++) {
        int row = m0 + ty*8 + i;
        if (row < NTOK) {
            #pragma unroll
            for (int j = 0; j < 4; j++) {
                int col = n0 + 32*j + 2*tx;
                float2 r = upk2(acc[i][j]);
                float2 o;
                o.x = __fadd_rn(r.x, bias[col]);
                o.y = __fadd_rn(r.y, bias[col+1]);
                *(float2*)&C[(size_t)row * HID + col] = o;
            }
        }
    }
}

__global__ __launch_bounds__(256, 2) void gemm_nt_kernel(
    const float* __restrict__ A, const float* __restrict__ W,
    const float* __restrict__ bias, float* __restrict__ C)
{
    gemm_nt_body(A, W, bias, C, blockIdx.x * 128, blockIdx.y * 128);
}

__global__ __launch_bounds__(256, 2) void gemm_qkv_kernel(
    const float* __restrict__ A,
    const float* __restrict__ Wq, const float* __restrict__ bq, float* __restrict__ Cq,
    const float* __restrict__ Wk, const float* __restrict__ bk, float* __restrict__ Ck,
    const float* __restrict__ Wv, const float* __restrict__ bv, float* __restrict__ Cv)
{
    const float* W; const float* bias; float* C;
    switch (blockIdx.z) {
        case 0: W = Wq; bias = bq; C = Cq; break;
        case 1: W = Wk; bias = bk; C = Ck; break;
        default: W = Wv; bias = bv; C = Cv; break;
    }
    gemm_nt_body(A, W, bias, C, blockIdx.x * 128, blockIdx.y * 128);
}

// ---------------- attention: EXACT Round-12-measured 451us version -------------
// scores: 4 k at a time (two f32x2 chains); separate exp pass; separate
// partial-sum pass (fully unrolled -> part[] in registers); single-k PV with
// inline div. Bit-identical numerics throughout.
__global__ __launch_bounds__(256, 2) void attn_kernel(
    const float* __restrict__ Q, const float* __restrict__ K,
    const float* __restrict__ V, float* __restrict__ OQ)
{
    extern __shared__ __align__(16) float sm[];
    float* Kt = sm;                    // [64][KPAD]  (transposed K)
    float* Vs = sm + HDIM * KPAD;      // [197][64]

    const int bh = blockIdx.x;
    const int b  = bh / NHEAD;
    const int h  = bh - b * NHEAD;
    const size_t base = (size_t)b * SEQ * HID + (size_t)h * HDIM;

    const float4* Kg = (const float4*)(K + base);
    const float4* Vg = (const float4*)(V + base);
    float4* Vs4 = (float4*)Vs;
    for (int i = threadIdx.x; i < SEQ * (HDIM/4); i += 256) {
        int r = i >> 4, c4 = (i & 15) * 4;
        size_t g = (size_t)r * (HID/4) + (c4 >> 2);
        float4 kv = Kg[g];
        Kt[(c4+0)*KPAD + r] = kv.x;
        Kt[(c4+1)*KPAD + r] = kv.y;
        Kt[(c4+2)*KPAD + r] = kv.z;
        Kt[(c4+3)*KPAD + r] = kv.w;
        Vs4[i] = Vg[g];
    }
    __syncthreads();

    const int q = threadIdx.x;
    if (q >= SEQ) return;

    float qr[HDIM];
    {
        const float4* Qp = (const float4*)(Q + base + (size_t)q * HID);
        #pragma unroll
        for (int i = 0; i < 16; i++) {
            float4 t = Qp[i];
            qr[4*i+0] = t.x; qr[4*i+1] = t.y; qr[4*i+2] = t.z; qr[4*i+3] = t.w;
        }
    }

    float sl[SEQ];
    float m = -3.402823466e+38f;

    // scores: 4 k at a time (two f32x2 chains), each lane = serial-d fma.rn chain
    #pragma unroll 1
    for (int k0 = 0; k0 < 196; k0 += 4) {
        ull a01 = 0ull, a23 = 0ull;
        #pragma unroll
        for (int d = 0; d < HDIM; d++) {
            ulonglong2 kk = *(const ulonglong2*)(Kt + d * KPAD + k0);
            ull qd2 = pk2(qr[d], qr[d]);
            fma2(a01, qd2, kk.x);
            fma2(a23, qd2, kk.y);
        }
        float2 s01 = upk2(a01);
        float2 s23 = upk2(a23);
        float v0 = __fmul_rn(s01.x, 0.125f);
        float v1 = __fmul_rn(s01.y, 0.125f);
        float v2 = __fmul_rn(s23.x, 0.125f);
        float v3 = __fmul_rn(s23.y, 0.125f);
        sl[k0+0] = v0; sl[k0+1] = v1; sl[k0+2] = v2; sl[k0+3] = v3;
        m = fmaxf(fmaxf(fmaxf(fmaxf(m, v0), v1), v2), v3);
    }
    {
        float a = 0.0f;
        #pragma unroll
        for (int d = 0; d < HDIM; d++)
            a = fmaf(qr[d], Kt[d * KPAD + 196], a);
        float v = __fmul_rn(a, 0.125f);
        sl[196] = v;
        m = fmaxf(m, v);
    }

    // u = exp(s - m)  (separate pass)
    for (int k = 0; k < SEQ; k++)
        sl[k] = expf(__fadd_rn(sl[k], -m));

    // l: strided partials + tree (XLA GPU row-reduction order) — separate pass
    float part[32];
    #pragma unroll
    for (int j = 0; j < 32; j++) part[j] = 0.0f;
    for (int k = 0; k < SEQ; k++)
        part[k & 31] = __fadd_rn(part[k & 31], sl[k]);
    #pragma unroll
    for (int off = 16; off >= 1; off >>= 1)
        #pragma unroll
        for (int j = 0; j < 16; j++)
            if (j < off) part[j] = __fadd_rn(part[j], part[j + off]);
    const float l = part[0];

    // PV with fused division (single-k); per-column ascending-k serial fma.rn
    ull acc[32];
    #pragma unroll
    for (int i = 0; i < 32; i++) acc[i] = 0ull;

    const ulonglong2* V2 = (const ulonglong2*)Vs;
    #pragma unroll 1
    for (int k = 0; k < SEQ; k++) {
        float p = __fdiv_rn(sl[k], l);
        ull pd = pk2(p, p);
        const ulonglong2* vr = V2 + (size_t)k * 16;
        #pragma unroll
        for (int i = 0; i < 16; i++) {
            ulonglong2 t = vr[i];
            fma2(acc[2*i],   pd, t.x);
            fma2(acc[2*i+1], pd, t.y);
        }
    }

    float* dst = OQ + base + (size_t)q * HID;
    #pragma unroll
    for (int i = 0; i < 32; i++) {
        float2 v = upk2(acc[i]);
        dst[2*i]   = qdq_m(v.x, 0.25f, 4.0f);
        dst[2*i+1] = qdq_m(v.y, 0.25f, 4.0f);
    }
}

// ---------------- launch: single stream ----------------------------------------
extern "C" void kernel_launch(void* const* d_in, const int* in_sizes, int n_in,
                              void* d_out, int out_size) {
    const float* x  = (const float*)d_in[0];
    const float* wq = (const float*)d_in[1];
    const float* bq = (const float*)d_in[2];
    const float* wk = (const float*)d_in[3];
    const float* bk = (const float*)d_in[4];
    const float* wv = (const float*)d_in[5];
    const float* bv = (const float*)d_in[6];
    const float* wo = (const float*)d_in[7];
    const float* bo = (const float*)d_in[8];
    float* out = (float*)d_out;

    float *XQ, *WQ, *WK, *WV, *WO, *Qb, *Kb, *Vb, *AQ;
    cudaGetSymbolAddress((void**)&XQ, g_XQ);
    cudaGetSymbolAddress((void**)&WQ, g_WQ);
    cudaGetSymbolAddress((void**)&WK, g_WK);
    cudaGetSymbolAddress((void**)&WV, g_WV);
    cudaGetSymbolAddress((void**)&WO, g_WO);
    cudaGetSymbolAddress((void**)&Qb, g_Q);
    cudaGetSymbolAddress((void**)&Kb, g_K);
    cudaGetSymbolAddress((void**)&Vb, g_V);
    cudaGetSymbolAddress((void**)&AQ, g_AQ);

    const int nX4 = NTOK * HID / 4;
    const int nW4 = HID * HID / 4;

    // 1) quantize-dequantize: X + 4 weights (fused)
    quant4_kernel<<<(nX4 + 255)/256, 256>>>((const float4*)x, (float4*)XQ, nX4, 0.25f, 4.0f);
    {
        dim3 wgrid((nW4 + 255)/256, 4);
        quantw_kernel<<<wgrid, 256>>>((const float4*)wq, (const float4*)wk,
                                      (const float4*)wv, (const float4*)wo,
                                      (float4*)WQ, (float4*)WK, (float4*)WV, (float4*)WO, nW4);
    }

    // 2) fused Q/K/V projections: 128x128 tiles, 99 ragged m-blocks
    dim3 qkvgrid(99, HID/128, 3);   // (99, 6, 3)
    gemm_qkv_kernel<<<qkvgrid, 256>>>(XQ, WQ, bq, Qb, WK, bk, Kb, WV, bv, Vb);

    // 3) attention; emits dequantized AO
    const int attn_smem = (HDIM * KPAD + SEQ * HDIM) * (int)sizeof(float);  // 101,632 B
    cudaFuncSetAttribute(attn_kernel, cudaFuncAttributeMaxDynamicSharedMemorySize, attn_smem);
    attn_kernel<<<BATCH * NHEAD, 256, attn_smem>>>(Qb, Kb, Vb, AQ);

    // 4) O-projection on dequantized AO
    dim3 ggrid(99, HID/128);        // (99, 6)
    gemm_nt_kernel<<<ggrid, 256>>>(AQ, WO, bo, out);
}